// round 3
// baseline (speedup 1.0000x reference)
#include <cuda_runtime.h>
#include <cstdint>

#define HIDDEN 1024
#define NHEADS 16
#define HDIM 64
#define BATCH 2
#define SEQ 2048
#define SCALE 0.03125f  /* HIDDEN^-0.5 */

// scratch (allocation-free rule: __device__ globals)
__device__ float g_q[BATCH * NHEADS * SEQ * HDIM];
__device__ float g_k[BATCH * NHEADS * SEQ * HDIM];
__device__ float g_v[BATCH * NHEADS * SEQ * HDIM];

// round-to-nearest fp32 -> tf32 (unbiased)
__device__ __forceinline__ float to_tf32(float x) {
    unsigned u;
    asm("cvt.rna.tf32.f32 %0, %1;" : "=r"(u) : "f"(x));
    return __uint_as_float(u);
}
__device__ __forceinline__ unsigned u_tf32(float x) {
    unsigned u;
    asm("cvt.rna.tf32.f32 %0, %1;" : "=r"(u) : "f"(x));
    return u;
}

// D += A*B, m16n8k8, tf32 inputs, f32 accumulate
__device__ __forceinline__ void mma_tf32(float c[4], const unsigned a[4], const unsigned b[2]) {
    asm volatile(
        "mma.sync.aligned.m16n8k8.row.col.f32.tf32.tf32.f32 "
        "{%0,%1,%2,%3},{%4,%5,%6,%7},{%8,%9},{%0,%1,%2,%3};\n"
        : "+f"(c[0]), "+f"(c[1]), "+f"(c[2]), "+f"(c[3])
        : "r"(a[0]), "r"(a[1]), "r"(a[2]), "r"(a[3]), "r"(b[0]), "r"(b[1]));
}

__device__ __forceinline__ void cp_async16(unsigned dst, const void* src) {
    asm volatile("cp.async.cg.shared.global [%0], [%1], 16;\n" :: "r"(dst), "l"(src));
}
__device__ __forceinline__ void cp_commit() { asm volatile("cp.async.commit_group;\n"); }
__device__ __forceinline__ void cp_wait1() { asm volatile("cp.async.wait_group 1;\n"); }
__device__ __forceinline__ void cp_wait0() { asm volatile("cp.async.wait_group 0;\n"); }

// ---------------------------------------------------------------------------
// Kernel 1: fused QKV projection (tf32 HMMA GEMM) — unchanged from R1.
// ---------------------------------------------------------------------------
__global__ __launch_bounds__(256) void qkv_kernel(const float* __restrict__ hidden,
                                                  const float* __restrict__ W) {
    __shared__ float As[128 * 36];
    __shared__ float Bs[32 * 68];

    const int h     = blockIdx.z;
    const int m0    = blockIdx.y * 128;
    const int cbase = blockIdx.x * 64;
    const int tid   = threadIdx.x;
    const int wid   = tid >> 5, lane = tid & 31;
    const int g     = lane >> 2, tg = lane & 3;
    const int wy    = wid & 3;
    const int wx    = wid >> 2;

    const float* Wh = W + (size_t)h * HIDDEN * 192;

    const int ar = tid >> 3;
    const int ak = (tid & 7) * 4;
    const int br = tid >> 4;
    const int bc = (tid & 15) * 4;

    float acc[2][4][4] = {};

    for (int k0 = 0; k0 < HIDDEN; k0 += 32) {
        float4 a[4], bv[2];
#pragma unroll
        for (int i = 0; i < 4; i++)
            a[i] = *(const float4*)&hidden[(size_t)(m0 + ar + 32 * i) * HIDDEN + k0 + ak];
        bv[0] = *(const float4*)&Wh[(size_t)(k0 + br) * 192 + cbase + bc];
        bv[1] = *(const float4*)&Wh[(size_t)(k0 + br + 16) * 192 + cbase + bc];

        __syncthreads();
#pragma unroll
        for (int i = 0; i < 4; i++) {
            float* d = &As[(ar + 32 * i) * 36 + ak];
            d[0] = to_tf32(a[i].x); d[1] = to_tf32(a[i].y);
            d[2] = to_tf32(a[i].z); d[3] = to_tf32(a[i].w);
        }
        {
            float* d0 = &Bs[br * 68 + bc];
            d0[0] = to_tf32(bv[0].x); d0[1] = to_tf32(bv[0].y);
            d0[2] = to_tf32(bv[0].z); d0[3] = to_tf32(bv[0].w);
            float* d1 = &Bs[(br + 16) * 68 + bc];
            d1[0] = to_tf32(bv[1].x); d1[1] = to_tf32(bv[1].y);
            d1[2] = to_tf32(bv[1].z); d1[3] = to_tf32(bv[1].w);
        }
        __syncthreads();

#pragma unroll
        for (int ks = 0; ks < 4; ks++) {
            const int kk = ks * 8;
            unsigned af[2][4];
#pragma unroll
            for (int mt = 0; mt < 2; mt++) {
                const int row = wy * 32 + mt * 16;
                af[mt][0] = __float_as_uint(As[(row + g) * 36 + kk + tg]);
                af[mt][1] = __float_as_uint(As[(row + g + 8) * 36 + kk + tg]);
                af[mt][2] = __float_as_uint(As[(row + g) * 36 + kk + tg + 4]);
                af[mt][3] = __float_as_uint(As[(row + g + 8) * 36 + kk + tg + 4]);
            }
#pragma unroll
            for (int nt = 0; nt < 4; nt++) {
                const int col = wx * 32 + nt * 8 + g;
                unsigned bf[2];
                bf[0] = __float_as_uint(Bs[(kk + tg) * 68 + col]);
                bf[1] = __float_as_uint(Bs[(kk + tg + 4) * 68 + col]);
#pragma unroll
                for (int mt = 0; mt < 2; mt++)
                    mma_tf32(acc[mt][nt], af[mt], bf);
            }
        }
    }

    float* dst = (cbase == 0) ? g_q : (cbase == 64 ? g_k : g_v);
#pragma unroll
    for (int mt = 0; mt < 2; mt++) {
        const int row = m0 + wy * 32 + mt * 16 + g;
        const int b = row >> 11, n = row & 2047;
#pragma unroll
        for (int nt = 0; nt < 4; nt++) {
            const int col = wx * 32 + nt * 8 + 2 * tg;
            const size_t base = (((size_t)(b * NHEADS + h)) * SEQ + n) * HDIM + col;
            *(float2*)&dst[base] = make_float2(acc[mt][nt][0], acc[mt][nt][1]);
            *(float2*)&dst[base + 8 * HDIM] = make_float2(acc[mt][nt][2], acc[mt][nt][3]);
        }
    }
}

// ---------------------------------------------------------------------------
// Kernel 2: flash attention v2 (tf32 HMMA).
// BQ=128, BKV=64, 256 thr / 8 warps. Warp w owns Q rows [16w,16w+16) x all 64 keys.
// - Q fragments live in registers (loaded once).
// - K/V/mask double-buffered in smem via cp.async.
// - Softmax fully warp-private (quad shuffles only).
// - P never touches smem: PV A-fragments built from S accumulators by quad shfl.
// smem layout (floats): K[2][64][68] @0, V[2][64][72] @8704, flags(int)[2][64] @17920
// ---------------------------------------------------------------------------
#define KSTR 68
#define VSTR 72
#define VBASE 8704
#define FLBASE 17920
#define FLASH_SMEM_FLOATS 18048

__global__ __launch_bounds__(256) void flash_kernel(const int* __restrict__ mask,
                                                    float* __restrict__ out) {
    extern __shared__ float sm[];
    int* smi = (int*)sm;
    const unsigned smbase = (unsigned)__cvta_generic_to_shared(sm);

    const int bh = blockIdx.y, b = bh >> 4, h = bh & 15;
    const int q0 = blockIdx.x * 128;
    const int tid = threadIdx.x, wid = tid >> 5, lane = tid & 31;
    const int g = lane >> 2, tg = lane & 3;
    const int row0 = wid * 16 + g, row1 = row0 + 8;

    const float* Qg = g_q + (size_t)bh * SEQ * HDIM;
    const float* Kg = g_k + (size_t)bh * SEQ * HDIM;
    const float* Vg = g_v + (size_t)bh * SEQ * HDIM;
    const int* maskb = mask + b * SEQ;

    // ---- stage Q (scaled, tf32) into K-buffer area, load frags, then free it
    {
        const int lr = tid >> 4, lc = (tid & 15) * 4;
#pragma unroll
        for (int i = 0; i < 8; i++) {
            float4 v = *(const float4*)&Qg[(size_t)(q0 + lr + 16 * i) * HDIM + lc];
            float* d = &sm[(lr + 16 * i) * KSTR + lc];
            d[0] = to_tf32(v.x * SCALE); d[1] = to_tf32(v.y * SCALE);
            d[2] = to_tf32(v.z * SCALE); d[3] = to_tf32(v.w * SCALE);
        }
    }
    __syncthreads();
    unsigned qa[8][4];
#pragma unroll
    for (int kc = 0; kc < 8; kc++) {
        const int kk = kc * 8;
        qa[kc][0] = __float_as_uint(sm[row0 * KSTR + kk + tg]);
        qa[kc][1] = __float_as_uint(sm[row1 * KSTR + kk + tg]);
        qa[kc][2] = __float_as_uint(sm[row0 * KSTR + kk + tg + 4]);
        qa[kc][3] = __float_as_uint(sm[row1 * KSTR + kk + tg + 4]);
    }
    __syncthreads();

    // ---- cp.async prefetch helpers (4 K-chunks + 4 V-chunks + flags / thread)
    const int crow = tid >> 4;              // 0..15 (+16*i)
    const int ccol = (tid & 15) * 4;
#define PREFETCH(buf, j0)                                                        \
    {                                                                            \
        _Pragma("unroll")                                                        \
        for (int i = 0; i < 4; i++) {                                            \
            int r = crow + 16 * i;                                               \
            cp_async16(smbase + (unsigned)(((buf) * 4352 + r * KSTR + ccol) * 4),\
                       &Kg[(size_t)((j0) + r) * HDIM + ccol]);                   \
            cp_async16(smbase + (unsigned)((VBASE + (buf) * 4608 + r * VSTR + ccol) * 4), \
                       &Vg[(size_t)((j0) + r) * HDIM + ccol]);                   \
        }                                                                        \
        if (tid < 16)                                                            \
            cp_async16(smbase + (unsigned)((FLBASE + (buf) * 64 + tid * 4) * 4), \
                       &maskb[(j0) + tid * 4]);                                  \
    }

    PREFETCH(0, 0);
    cp_commit();

    float m0r = -1e30f, m1r = -1e30f, l0r = 0.f, l1r = 0.f;
    float o[8][4] = {};
    float s[8][4];

    const int sbase = lane & ~3;
    const int s0l = sbase + (tg >> 1);
    const int s2l = s0l + 2;
    const int e = tg & 1;

    for (int it = 0; it < 32; ++it) {
        const int c = it & 1;
        const int kb = c * 4352;
        const int vb = VBASE + c * 4608;

        if (it + 1 < 32) { PREFETCH(c ^ 1, (it + 1) * 64); cp_commit(); cp_wait1(); }
        else cp_wait0();
        __syncthreads();   // buf c ready for everyone

        // ---- S = Q K^T ----
#pragma unroll
        for (int nt = 0; nt < 8; nt++) { s[nt][0] = 0.f; s[nt][1] = 0.f; s[nt][2] = 0.f; s[nt][3] = 0.f; }
#pragma unroll
        for (int kc = 0; kc < 8; kc++) {
            const int kk = kc * 8;
#pragma unroll
            for (int nt = 0; nt < 8; nt++) {
                unsigned bf[2];
                bf[0] = u_tf32(sm[kb + (nt * 8 + g) * KSTR + kk + tg]);
                bf[1] = u_tf32(sm[kb + (nt * 8 + g) * KSTR + kk + tg + 4]);
                mma_tf32(s[nt], qa[kc], bf);
            }
        }

        // ---- mask + warp-private row max ----
        float fl[8][2];
        float mx0 = -1e30f, mx1 = -1e30f;
#pragma unroll
        for (int nt = 0; nt < 8; nt++) {
            const int cb = nt * 8 + 2 * tg;
            fl[nt][0] = (smi[FLBASE + c * 64 + cb] != 0) ? 1.f : 0.f;
            fl[nt][1] = (smi[FLBASE + c * 64 + cb + 1] != 0) ? 1.f : 0.f;
            if (fl[nt][0] == 0.f) { s[nt][0] = -1e30f; s[nt][2] = -1e30f; }
            if (fl[nt][1] == 0.f) { s[nt][1] = -1e30f; s[nt][3] = -1e30f; }
            mx0 = fmaxf(mx0, fmaxf(s[nt][0], s[nt][1]));
            mx1 = fmaxf(mx1, fmaxf(s[nt][2], s[nt][3]));
        }
        mx0 = fmaxf(mx0, __shfl_xor_sync(0xffffffffu, mx0, 1));
        mx0 = fmaxf(mx0, __shfl_xor_sync(0xffffffffu, mx0, 2));
        mx1 = fmaxf(mx1, __shfl_xor_sync(0xffffffffu, mx1, 1));
        mx1 = fmaxf(mx1, __shfl_xor_sync(0xffffffffu, mx1, 2));

        const float mn0 = fmaxf(m0r, mx0), mn1 = fmaxf(m1r, mx1);
        const float f0 = __expf(m0r - mn0), f1 = __expf(m1r - mn1);
        m0r = mn0; m1r = mn1;

        // ---- P = exp(S - m) (stays in registers, tf32-rounded), row sums ----
        float ps0 = 0.f, ps1 = 0.f;
#pragma unroll
        for (int nt = 0; nt < 8; nt++) {
            float p0 = __expf(s[nt][0] - mn0) * fl[nt][0];
            float p1 = __expf(s[nt][1] - mn0) * fl[nt][1];
            float p2 = __expf(s[nt][2] - mn1) * fl[nt][0];
            float p3 = __expf(s[nt][3] - mn1) * fl[nt][1];
            ps0 += p0 + p1; ps1 += p2 + p3;
            s[nt][0] = to_tf32(p0); s[nt][1] = to_tf32(p1);
            s[nt][2] = to_tf32(p2); s[nt][3] = to_tf32(p3);
        }
        ps0 += __shfl_xor_sync(0xffffffffu, ps0, 1);
        ps0 += __shfl_xor_sync(0xffffffffu, ps0, 2);
        ps1 += __shfl_xor_sync(0xffffffffu, ps1, 1);
        ps1 += __shfl_xor_sync(0xffffffffu, ps1, 2);
        l0r = l0r * f0 + ps0;
        l1r = l1r * f1 + ps1;

#pragma unroll
        for (int nt = 0; nt < 8; nt++) {
            o[nt][0] *= f0; o[nt][1] *= f0;
            o[nt][2] *= f1; o[nt][3] *= f1;
        }

        // ---- O += P V : A-fragments of P built via quad shuffles ----
#pragma unroll
        for (int kc = 0; kc < 8; kc++) {
            const int kk = kc * 8;
            float v00 = __shfl_sync(0xffffffffu, s[kc][0], s0l);
            float v01 = __shfl_sync(0xffffffffu, s[kc][1], s0l);
            float v02 = __shfl_sync(0xffffffffu, s[kc][2], s0l);
            float v03 = __shfl_sync(0xffffffffu, s[kc][3], s0l);
            float v20 = __shfl_sync(0xffffffffu, s[kc][0], s2l);
            float v21 = __shfl_sync(0xffffffffu, s[kc][1], s2l);
            float v22 = __shfl_sync(0xffffffffu, s[kc][2], s2l);
            float v23 = __shfl_sync(0xffffffffu, s[kc][3], s2l);
            unsigned ap[4];
            ap[0] = __float_as_uint(e ? v01 : v00);   // (row g,   col kk+tg)
            ap[1] = __float_as_uint(e ? v03 : v02);   // (row g+8, col kk+tg)
            ap[2] = __float_as_uint(e ? v21 : v20);   // (row g,   col kk+tg+4)
            ap[3] = __float_as_uint(e ? v23 : v22);   // (row g+8, col kk+tg+4)
#pragma unroll
            for (int nt = 0; nt < 8; nt++) {
                unsigned bf[2];
                bf[0] = u_tf32(sm[vb + (kk + tg) * VSTR + nt * 8 + g]);
                bf[1] = u_tf32(sm[vb + (kk + tg + 4) * VSTR + nt * 8 + g]);
                mma_tf32(o[nt], ap, bf);
            }
        }
        __syncthreads();   // all reads of buf c done -> next iter may overwrite c^1 safely
    }

    const float inv0 = 1.f / l0r, inv1 = 1.f / l1r;
#pragma unroll
    for (int nt = 0; nt < 8; nt++) {
        const int col = h * HDIM + nt * 8 + 2 * tg;
        const size_t o0 = ((size_t)(b * SEQ + q0 + row0)) * HIDDEN + col;
        const size_t o1 = ((size_t)(b * SEQ + q0 + row1)) * HIDDEN + col;
        *(float2*)&out[o0] = make_float2(o[nt][0] * inv0, o[nt][1] * inv0);
        *(float2*)&out[o1] = make_float2(o[nt][2] * inv1, o[nt][3] * inv1);
    }
}

// ---------------------------------------------------------------------------
extern "C" void kernel_launch(void* const* d_in, const int* in_sizes, int n_in,
                              void* d_out, int out_size) {
    const float* hidden = (const float*)d_in[0];   // [2, 2048, 1024] f32
    const int*   amask  = (const int*)d_in[1];     // [2, 2048] i32
    const float* W      = (const float*)d_in[2];   // [16, 1024, 192] f32
    float* out = (float*)d_out;                    // [2, 2048, 1024] f32
    (void)in_sizes; (void)n_in; (void)out_size;

    const int flash_smem = FLASH_SMEM_FLOATS * sizeof(float);   // 72192 B
    cudaFuncSetAttribute(flash_kernel, cudaFuncAttributeMaxDynamicSharedMemorySize,
                         flash_smem);

    qkv_kernel<<<dim3(3, 32, 16), 256>>>(hidden, W);
    flash_kernel<<<dim3(SEQ / 128, BATCH * NHEADS), 256, flash_smem>>>(amask, out);
}

// round 4
// speedup vs baseline: 1.2876x; 1.2876x over previous
#include <cuda_runtime.h>
#include <cstdint>

#define HIDDEN 1024
#define NHEADS 16
#define HDIM 64
#define BATCH 2
#define SEQ 2048
#define SCALE 0.03125f  /* HIDDEN^-0.5 */

// scratch (allocation-free rule: __device__ globals)
__device__ float g_q[BATCH * NHEADS * SEQ * HDIM];
__device__ float g_k[BATCH * NHEADS * SEQ * HDIM];
__device__ float g_v[BATCH * NHEADS * SEQ * HDIM];
__device__ float g_hid[BATCH * SEQ * HIDDEN];        // tf32-rounded hidden
__device__ float g_wt[NHEADS * HIDDEN * 3 * HDIM];   // tf32-rounded W

__device__ __forceinline__ float to_tf32(float x) {
    unsigned u;
    asm("cvt.rna.tf32.f32 %0, %1;" : "=r"(u) : "f"(x));
    return __uint_as_float(u);
}

// D += A*B, m16n8k8, tf32 inputs, f32 accumulate
__device__ __forceinline__ void mma_tf32(float c[4], const unsigned a[4], const unsigned b[2]) {
    asm volatile(
        "mma.sync.aligned.m16n8k8.row.col.f32.tf32.tf32.f32 "
        "{%0,%1,%2,%3},{%4,%5,%6,%7},{%8,%9},{%0,%1,%2,%3};\n"
        : "+f"(c[0]), "+f"(c[1]), "+f"(c[2]), "+f"(c[3])
        : "r"(a[0]), "r"(a[1]), "r"(a[2]), "r"(a[3]), "r"(b[0]), "r"(b[1]));
}

__device__ __forceinline__ void cp_async16(unsigned dst, const void* src) {
    asm volatile("cp.async.cg.shared.global [%0], [%1], 16;\n" :: "r"(dst), "l"(src));
}
__device__ __forceinline__ void cp_commit() { asm volatile("cp.async.commit_group;\n"); }
__device__ __forceinline__ void cp_wait1() { asm volatile("cp.async.wait_group 1;\n"); }
__device__ __forceinline__ void cp_wait0() { asm volatile("cp.async.wait_group 0;\n"); }

// ---------------------------------------------------------------------------
// Kernel 0: round fp32 tensor to tf32 once (amortizes all mainloop cvts).
// ---------------------------------------------------------------------------
__global__ __launch_bounds__(256) void cvt_kernel(const float* __restrict__ src,
                                                  float* __restrict__ dst, int n4) {
    int i = blockIdx.x * blockDim.x + threadIdx.x;
    int stride = gridDim.x * blockDim.x;
    for (; i < n4; i += stride) {
        float4 v = ((const float4*)src)[i];
        v.x = to_tf32(v.x); v.y = to_tf32(v.y);
        v.z = to_tf32(v.z); v.w = to_tf32(v.w);
        ((float4*)dst)[i] = v;
    }
}

// ---------------------------------------------------------------------------
// Kernel 1: fused QKV projection (tf32 HMMA), cp.async double-buffered.
// Inputs pre-rounded; epilogue rounds Q/K/V for the flash kernel.
// smem words: As[2][128*36] @0, Bs[2][32*68] @9216; total 13568 (54.3 KB)
// ---------------------------------------------------------------------------
#define QAS_W 4608
#define QBS_BASE 9216
#define QBS_W 2176
#define QKV_SMEM_FLOATS 13568

__global__ __launch_bounds__(256) void qkv_kernel(const float* __restrict__ hidden,
                                                  const float* __restrict__ W) {
    extern __shared__ float qsm[];
    const unsigned smb = (unsigned)__cvta_generic_to_shared(qsm);

    const int h     = blockIdx.z;
    const int m0    = blockIdx.y * 128;
    const int cbase = blockIdx.x * 64;
    const int tid   = threadIdx.x;
    const int wid   = tid >> 5, lane = tid & 31;
    const int g     = lane >> 2, tg = lane & 3;
    const int wy    = wid & 3;
    const int wx    = wid >> 2;

    const float* Wh = W + (size_t)h * HIDDEN * 192;

    const int ar = tid >> 3;
    const int ak = (tid & 7) * 4;
    const int br = tid >> 4;
    const int bc = (tid & 15) * 4;

#define QKV_PREF(buf, k0)                                                          \
    {                                                                              \
        _Pragma("unroll")                                                          \
        for (int i = 0; i < 4; i++)                                                \
            cp_async16(smb + (unsigned)(((buf) * QAS_W + (ar + 32 * i) * 36 + ak) * 4), \
                       &hidden[(size_t)(m0 + ar + 32 * i) * HIDDEN + (k0) + ak]);  \
        cp_async16(smb + (unsigned)((QBS_BASE + (buf) * QBS_W + br * 68 + bc) * 4),\
                   &Wh[(size_t)((k0) + br) * 192 + cbase + bc]);                   \
        cp_async16(smb + (unsigned)((QBS_BASE + (buf) * QBS_W + (br + 16) * 68 + bc) * 4), \
                   &Wh[(size_t)((k0) + br + 16) * 192 + cbase + bc]);              \
    }

    QKV_PREF(0, 0);
    cp_commit();

    float acc[2][4][4] = {};

    for (int kt = 0; kt < HIDDEN / 32; kt++) {
        const int c = kt & 1;
        if (kt + 1 < HIDDEN / 32) { QKV_PREF(c ^ 1, (kt + 1) * 32); cp_commit(); cp_wait1(); }
        else cp_wait0();
        __syncthreads();

        const float* As = qsm + c * QAS_W;
        const float* Bs = qsm + QBS_BASE + c * QBS_W;

#pragma unroll
        for (int ks = 0; ks < 4; ks++) {
            const int kk = ks * 8;
            unsigned af[2][4];
#pragma unroll
            for (int mt = 0; mt < 2; mt++) {
                const int row = wy * 32 + mt * 16;
                af[mt][0] = __float_as_uint(As[(row + g) * 36 + kk + tg]);
                af[mt][1] = __float_as_uint(As[(row + g + 8) * 36 + kk + tg]);
                af[mt][2] = __float_as_uint(As[(row + g) * 36 + kk + tg + 4]);
                af[mt][3] = __float_as_uint(As[(row + g + 8) * 36 + kk + tg + 4]);
            }
#pragma unroll
            for (int nt = 0; nt < 4; nt++) {
                const int col = wx * 32 + nt * 8 + g;
                unsigned bf[2];
                bf[0] = __float_as_uint(Bs[(kk + tg) * 68 + col]);
                bf[1] = __float_as_uint(Bs[(kk + tg + 4) * 68 + col]);
#pragma unroll
                for (int mt = 0; mt < 2; mt++)
                    mma_tf32(acc[mt][nt], af[mt], bf);
            }
        }
        __syncthreads();   // reads of buf c done before it is refilled
    }

    float* dst = (cbase == 0) ? g_q : (cbase == 64 ? g_k : g_v);
#pragma unroll
    for (int mt = 0; mt < 2; mt++) {
        const int row = m0 + wy * 32 + mt * 16 + g;
        const int b = row >> 11, n = row & 2047;
#pragma unroll
        for (int nt = 0; nt < 4; nt++) {
            const int col = wx * 32 + nt * 8 + 2 * tg;
            const size_t base = (((size_t)(b * NHEADS + h)) * SEQ + n) * HDIM + col;
            *(float2*)&dst[base] = make_float2(to_tf32(acc[mt][nt][0]), to_tf32(acc[mt][nt][1]));
            *(float2*)&dst[base + 8 * HDIM] = make_float2(to_tf32(acc[mt][nt][2]), to_tf32(acc[mt][nt][3]));
        }
    }
}

// ---------------------------------------------------------------------------
// Kernel 2: flash attention (tf32 HMMA), BQ=128, BKV=64, 8 warps.
// Warp owns 16 Q rows x all 64 keys -> softmax warp-private.
// K/V/mask double-buffered via cp.async (data already tf32-clean -> no cvts).
// P stays in registers (quad-shuffle transpose for the PV A-fragments).
// smem floats: K[2][64][68] @0, V[2][64][72] @8704, flags(int)[2][64] @17920
// ---------------------------------------------------------------------------
#define KSTR 68
#define VSTR 72
#define VBASE 8704
#define FLBASE 17920
#define FLASH_SMEM_FLOATS 18048

__global__ __launch_bounds__(256, 2) void flash_kernel(const int* __restrict__ mask,
                                                       float* __restrict__ out) {
    extern __shared__ float sm[];
    int* smi = (int*)sm;
    const unsigned smbase = (unsigned)__cvta_generic_to_shared(sm);

    const int bh = blockIdx.y, b = bh >> 4, h = bh & 15;
    const int q0 = blockIdx.x * 128;
    const int tid = threadIdx.x, wid = tid >> 5, lane = tid & 31;
    const int g = lane >> 2, tg = lane & 3;
    const int row0 = wid * 16 + g, row1 = row0 + 8;

    const float* Qg = g_q + (size_t)bh * SEQ * HDIM;
    const float* Kg = g_k + (size_t)bh * SEQ * HDIM;
    const float* Vg = g_v + (size_t)bh * SEQ * HDIM;
    const int* maskb = mask + b * SEQ;

    // stage Q (x SCALE, exact pow2) into smem, pull frags to regs, free buffer
    {
        const int lr = tid >> 4, lc = (tid & 15) * 4;
#pragma unroll
        for (int i = 0; i < 8; i++) {
            float4 v = *(const float4*)&Qg[(size_t)(q0 + lr + 16 * i) * HDIM + lc];
            float* d = &sm[(lr + 16 * i) * KSTR + lc];
            d[0] = v.x * SCALE; d[1] = v.y * SCALE;
            d[2] = v.z * SCALE; d[3] = v.w * SCALE;
        }
    }
    __syncthreads();
    unsigned qa[8][4];
#pragma unroll
    for (int kc = 0; kc < 8; kc++) {
        const int kk = kc * 8;
        qa[kc][0] = __float_as_uint(sm[row0 * KSTR + kk + tg]);
        qa[kc][1] = __float_as_uint(sm[row1 * KSTR + kk + tg]);
        qa[kc][2] = __float_as_uint(sm[row0 * KSTR + kk + tg + 4]);
        qa[kc][3] = __float_as_uint(sm[row1 * KSTR + kk + tg + 4]);
    }
    __syncthreads();

    const int crow = tid >> 4;
    const int ccol = (tid & 15) * 4;
#define PREFETCH(buf, j0)                                                        \
    {                                                                            \
        _Pragma("unroll")                                                        \
        for (int i = 0; i < 4; i++) {                                            \
            int r = crow + 16 * i;                                               \
            cp_async16(smbase + (unsigned)(((buf) * 4352 + r * KSTR + ccol) * 4),\
                       &Kg[(size_t)((j0) + r) * HDIM + ccol]);                   \
            cp_async16(smbase + (unsigned)((VBASE + (buf) * 4608 + r * VSTR + ccol) * 4), \
                       &Vg[(size_t)((j0) + r) * HDIM + ccol]);                   \
        }                                                                        \
        if (tid < 16)                                                            \
            cp_async16(smbase + (unsigned)((FLBASE + (buf) * 64 + tid * 4) * 4), \
                       &maskb[(j0) + tid * 4]);                                  \
    }

    PREFETCH(0, 0);
    cp_commit();

    float m0r = -1e30f, m1r = -1e30f, l0r = 0.f, l1r = 0.f;
    float o[8][4] = {};
    float s[8][4];

    const int s0l = (lane & ~3) + (tg >> 1);
    const int s2l = s0l + 2;
    const int e = tg & 1;

    for (int it = 0; it < 32; ++it) {
        const int c = it & 1;
        const int kb = c * 4352;
        const int vb = VBASE + c * 4608;

        if (it + 1 < 32) { PREFETCH(c ^ 1, (it + 1) * 64); cp_commit(); cp_wait1(); }
        else cp_wait0();
        __syncthreads();   // buf c ready

        // ---- S = Q K^T ----
#pragma unroll
        for (int nt = 0; nt < 8; nt++) { s[nt][0] = 0.f; s[nt][1] = 0.f; s[nt][2] = 0.f; s[nt][3] = 0.f; }
#pragma unroll
        for (int kc = 0; kc < 8; kc++) {
            const int kk = kc * 8;
#pragma unroll
            for (int nt = 0; nt < 8; nt++) {
                unsigned bf[2];
                bf[0] = __float_as_uint(sm[kb + (nt * 8 + g) * KSTR + kk + tg]);
                bf[1] = __float_as_uint(sm[kb + (nt * 8 + g) * KSTR + kk + tg + 4]);
                mma_tf32(s[nt], qa[kc], bf);
            }
        }

        // ---- mask (-1e30; expf underflows to exact 0) + warp-private max ----
        float mx0 = -1e30f, mx1 = -1e30f;
#pragma unroll
        for (int nt = 0; nt < 8; nt++) {
            const int cb = nt * 8 + 2 * tg;
            if (smi[FLBASE + c * 64 + cb] == 0)     { s[nt][0] = -1e30f; s[nt][2] = -1e30f; }
            if (smi[FLBASE + c * 64 + cb + 1] == 0) { s[nt][1] = -1e30f; s[nt][3] = -1e30f; }
            mx0 = fmaxf(mx0, fmaxf(s[nt][0], s[nt][1]));
            mx1 = fmaxf(mx1, fmaxf(s[nt][2], s[nt][3]));
        }
        mx0 = fmaxf(mx0, __shfl_xor_sync(0xffffffffu, mx0, 1));
        mx0 = fmaxf(mx0, __shfl_xor_sync(0xffffffffu, mx0, 2));
        mx1 = fmaxf(mx1, __shfl_xor_sync(0xffffffffu, mx1, 1));
        mx1 = fmaxf(mx1, __shfl_xor_sync(0xffffffffu, mx1, 2));

        const float mn0 = fmaxf(m0r, mx0), mn1 = fmaxf(m1r, mx1);
        const float f0 = __expf(m0r - mn0), f1 = __expf(m1r - mn1);
        m0r = mn0; m1r = mn1;

        // ---- P = exp(S - m) in registers (tf32-rounded), row sums ----
        float ps0 = 0.f, ps1 = 0.f;
#pragma unroll
        for (int nt = 0; nt < 8; nt++) {
            float p0 = __expf(s[nt][0] - mn0);
            float p1 = __expf(s[nt][1] - mn0);
            float p2 = __expf(s[nt][2] - mn1);
            float p3 = __expf(s[nt][3] - mn1);
            ps0 += p0 + p1; ps1 += p2 + p3;
            s[nt][0] = to_tf32(p0); s[nt][1] = to_tf32(p1);
            s[nt][2] = to_tf32(p2); s[nt][3] = to_tf32(p3);
        }
        ps0 += __shfl_xor_sync(0xffffffffu, ps0, 1);
        ps0 += __shfl_xor_sync(0xffffffffu, ps0, 2);
        ps1 += __shfl_xor_sync(0xffffffffu, ps1, 1);
        ps1 += __shfl_xor_sync(0xffffffffu, ps1, 2);
        l0r = l0r * f0 + ps0;
        l1r = l1r * f1 + ps1;

#pragma unroll
        for (int nt = 0; nt < 8; nt++) {
            o[nt][0] *= f0; o[nt][1] *= f0;
            o[nt][2] *= f1; o[nt][3] *= f1;
        }

        // ---- O += P V : P A-fragments via quad shuffles ----
#pragma unroll
        for (int kc = 0; kc < 8; kc++) {
            const int kk = kc * 8;
            float v00 = __shfl_sync(0xffffffffu, s[kc][0], s0l);
            float v01 = __shfl_sync(0xffffffffu, s[kc][1], s0l);
            float v02 = __shfl_sync(0xffffffffu, s[kc][2], s0l);
            float v03 = __shfl_sync(0xffffffffu, s[kc][3], s0l);
            float v20 = __shfl_sync(0xffffffffu, s[kc][0], s2l);
            float v21 = __shfl_sync(0xffffffffu, s[kc][1], s2l);
            float v22 = __shfl_sync(0xffffffffu, s[kc][2], s2l);
            float v23 = __shfl_sync(0xffffffffu, s[kc][3], s2l);
            unsigned ap[4];
            ap[0] = __float_as_uint(e ? v01 : v00);
            ap[1] = __float_as_uint(e ? v03 : v02);
            ap[2] = __float_as_uint(e ? v21 : v20);
            ap[3] = __float_as_uint(e ? v23 : v22);
#pragma unroll
            for (int nt = 0; nt < 8; nt++) {
                unsigned bf[2];
                bf[0] = __float_as_uint(sm[vb + (kk + tg) * VSTR + nt * 8 + g]);
                bf[1] = __float_as_uint(sm[vb + (kk + tg + 4) * VSTR + nt * 8 + g]);
                mma_tf32(o[nt], ap, bf);
            }
        }
        __syncthreads();   // reads of buf c done
    }

    const float inv0 = 1.f / l0r, inv1 = 1.f / l1r;
#pragma unroll
    for (int nt = 0; nt < 8; nt++) {
        const int col = h * HDIM + nt * 8 + 2 * tg;
        const size_t o0 = ((size_t)(b * SEQ + q0 + row0)) * HIDDEN + col;
        const size_t o1 = ((size_t)(b * SEQ + q0 + row1)) * HIDDEN + col;
        *(float2*)&out[o0] = make_float2(o[nt][0] * inv0, o[nt][1] * inv0);
        *(float2*)&out[o1] = make_float2(o[nt][2] * inv1, o[nt][3] * inv1);
    }
}

// ---------------------------------------------------------------------------
extern "C" void kernel_launch(void* const* d_in, const int* in_sizes, int n_in,
                              void* d_out, int out_size) {
    const float* hidden = (const float*)d_in[0];   // [2, 2048, 1024] f32
    const int*   amask  = (const int*)d_in[1];     // [2, 2048] i32
    const float* W      = (const float*)d_in[2];   // [16, 1024, 192] f32
    float* out = (float*)d_out;                    // [2, 2048, 1024] f32
    (void)in_sizes; (void)n_in; (void)out_size;

    float* hid_t; float* w_t;
    cudaGetSymbolAddress((void**)&hid_t, g_hid);
    cudaGetSymbolAddress((void**)&w_t, g_wt);

    const int qkv_smem = QKV_SMEM_FLOATS * sizeof(float);      // 54272 B
    const int flash_smem = FLASH_SMEM_FLOATS * sizeof(float);  // 72192 B
    cudaFuncSetAttribute(qkv_kernel, cudaFuncAttributeMaxDynamicSharedMemorySize, qkv_smem);
    cudaFuncSetAttribute(flash_kernel, cudaFuncAttributeMaxDynamicSharedMemorySize, flash_smem);

    cvt_kernel<<<1024, 256>>>(hidden, hid_t, BATCH * SEQ * HIDDEN / 4);
    cvt_kernel<<<1024, 256>>>(W, w_t, NHEADS * HIDDEN * 3 * HDIM / 4);
    qkv_kernel<<<dim3(3, 32, 16), 256, qkv_smem>>>(hid_t, w_t);
    flash_kernel<<<dim3(SEQ / 128, BATCH * NHEADS), 256, flash_smem>>>(amask, out);
}